// round 2
// baseline (speedup 1.0000x reference)
#include <cuda_runtime.h>
#include <cstdint>

// Problem constants (fixed dataset)
#define FDIM 512
#define EMAX 256

// ---- device scratch (no allocs allowed) ----
__device__ int   g_nactive;
__device__ int   g_nchunks;
__device__ int   g_eidx[EMAX];
__device__ float g_ta[EMAX];     // trunc(alpha) for compacted estimators, 0 in padding
__device__ float g_bias[EMAX];   // bias for compacted estimators, 0 in padding
__device__ float g_Wa[EMAX * FDIM];  // compacted W rows (zero rows in padding)

// ---- packed f32x2 helpers (Blackwell) ----
__device__ __forceinline__ unsigned long long pk2(float a, float b) {
    unsigned long long r;
    asm("mov.b64 %0, {%1, %2};" : "=l"(r) : "f"(a), "f"(b));
    return r;
}
__device__ __forceinline__ void fma2(unsigned long long& c, unsigned long long a, unsigned long long b) {
    asm("fma.rn.f32x2 %0, %1, %2, %0;" : "+l"(c) : "l"(a), "l"(b));
}
__device__ __forceinline__ void upk2(unsigned long long p, float& a, float& b) {
    asm("mov.b64 {%0, %1}, %2;" : "=f"(a), "=f"(b) : "l"(p));
}

// ============================================================
// Kernel 1: compact active estimators (trunc(alpha) != 0)
// Single block of 256 threads. Deterministic (no cross-block atomics).
// ============================================================
__global__ void prep_kernel(const float* __restrict__ alphas,
                            const float* __restrict__ bias,
                            int E) {
    int e = threadIdx.x;
    float ta = 0.f, bi = 0.f;
    int flag = 0;
    if (e < E) {
        float a = alphas[e];
        bi = bias[e];
        ta = truncf(a);
        flag = (ta != 0.f) ? 1 : 0;
    }
    unsigned mask = __ballot_sync(0xffffffffu, flag);
    int lane = e & 31;
    int warp = e >> 5;
    int prefix = __popc(mask & ((1u << lane) - 1u));
    int wtotal = __popc(mask);

    __shared__ int wtot[8];
    __shared__ int woff[8];
    if (lane == 0) wtot[warp] = wtotal;
    __syncthreads();
    if (e == 0) {
        int s = 0;
        for (int i = 0; i < 8; i++) { woff[i] = s; s += wtot[i]; }
        g_nactive = s;
        int nc = (s + 31) / 32;
        if (nc < 1) nc = 1;
        g_nchunks = nc;
    }
    // zero-init pads (overwritten below for active slots after sync)
    g_ta[e] = 0.f;
    g_bias[e] = 0.f;
    g_eidx[e] = 0;
    __syncthreads();
    if (flag) {
        int pos = woff[warp] + prefix;
        g_eidx[pos] = e;
        g_ta[pos] = ta;
        g_bias[pos] = bi;
    }
}

// ============================================================
// Kernel 2: pack active W rows contiguously (zero the padding rows)
// grid = EMAX blocks of 128 threads; each block handles one compacted row.
// ============================================================
__global__ void packW_kernel(const float* __restrict__ W) {
    int p = blockIdx.x;
    int na = g_nactive;
    int npad = g_nchunks * 32;
    if (p >= npad) return;
    float4* dst = reinterpret_cast<float4*>(g_Wa + (size_t)p * FDIM);
    if (p < na) {
        int e = g_eidx[p];
        const float4* src = reinterpret_cast<const float4*>(W + (size_t)e * FDIM);
        dst[threadIdx.x] = src[threadIdx.x];
    } else {
        float4 z = {0.f, 0.f, 0.f, 0.f};
        dst[threadIdx.x] = z;
    }
}

// ============================================================
// Kernel 3: main — per 128-row block, loop over 32-estimator chunks,
// fp32 dot products via packed f32x2 FMA, accumulate sign votes.
// ============================================================
#define BR 128            // rows per block
#define BE 32             // estimators per chunk
#define KB 32             // F-chunk size
#define XS (BR + 4)       // x_s row stride (floats), keeps float4 alignment
#define WS (BE + 4)       // w_s row stride

__global__ __launch_bounds__(256) void main_kernel(const float* __restrict__ x,
                                                   float* __restrict__ out,
                                                   int N) {
    __shared__ float x_s[KB * XS];
    __shared__ float w_s[KB * WS];

    const int t = threadIdx.x;
    const int rowBase = blockIdx.x * BR;
    const int et = t & 7;        // 0..7  : estimator-thread
    const int rt = t >> 3;       // 0..31 : row-thread (4 rows each)

    float rowsum0 = 0.f, rowsum1 = 0.f, rowsum2 = 0.f, rowsum3 = 0.f;
    const int nchunks = g_nchunks;

    for (int ec = 0; ec < nchunks; ec++) {
        unsigned long long acc[2][4];
#pragma unroll
        for (int a = 0; a < 2; a++)
#pragma unroll
            for (int j = 0; j < 4; j++) acc[a][j] = 0ull;

        for (int fc = 0; fc < FDIM / KB; fc++) {
            // ---- load x tile [KB x BR] transposed ----
#pragma unroll
            for (int i = 0; i < 4; i++) {
                int idx = t + i * 256;        // 0..1023
                int r = idx >> 3;             // 0..127
                int fq = idx & 7;             // 0..7
                float4 v = {0.f, 0.f, 0.f, 0.f};
                int gr = rowBase + r;
                if (gr < N) {
                    v = *reinterpret_cast<const float4*>(
                        x + (size_t)gr * FDIM + fc * KB + fq * 4);
                }
                x_s[(fq * 4 + 0) * XS + r] = v.x;
                x_s[(fq * 4 + 1) * XS + r] = v.y;
                x_s[(fq * 4 + 2) * XS + r] = v.z;
                x_s[(fq * 4 + 3) * XS + r] = v.w;
            }
            // ---- load w tile [KB x BE] transposed ----
            {
                int e = t >> 3;               // 0..31
                int fq = t & 7;               // 0..7
                float4 v = *reinterpret_cast<const float4*>(
                    g_Wa + (size_t)(ec * BE + e) * FDIM + fc * KB + fq * 4);
                w_s[(fq * 4 + 0) * WS + e] = v.x;
                w_s[(fq * 4 + 1) * WS + e] = v.y;
                w_s[(fq * 4 + 2) * WS + e] = v.z;
                w_s[(fq * 4 + 3) * WS + e] = v.w;
            }
            __syncthreads();

#pragma unroll
            for (int k = 0; k < KB; k++) {
                float4 xv = *reinterpret_cast<const float4*>(&x_s[k * XS + rt * 4]);
                float4 wv = *reinterpret_cast<const float4*>(&w_s[k * WS + et * 4]);
                unsigned long long xp0 = pk2(xv.x, xv.y);
                unsigned long long xp1 = pk2(xv.z, xv.w);
                unsigned long long w0 = pk2(wv.x, wv.x);
                unsigned long long w1 = pk2(wv.y, wv.y);
                unsigned long long w2 = pk2(wv.z, wv.z);
                unsigned long long w3 = pk2(wv.w, wv.w);
                fma2(acc[0][0], xp0, w0);
                fma2(acc[1][0], xp1, w0);
                fma2(acc[0][1], xp0, w1);
                fma2(acc[1][1], xp1, w1);
                fma2(acc[0][2], xp0, w2);
                fma2(acc[1][2], xp1, w2);
                fma2(acc[0][3], xp0, w3);
                fma2(acc[1][3], xp1, w3);
            }
            __syncthreads();
        }

        // ---- chunk epilogue: threshold + weighted vote ----
#pragma unroll
        for (int j = 0; j < 4; j++) {
            int e = ec * BE + et * 4 + j;
            float bias = g_bias[e];
            float ta = g_ta[e];
            float d0, d1, d2, d3;
            upk2(acc[0][j], d0, d1);
            upk2(acc[1][j], d2, d3);
            if (d0 + bias > 0.f) rowsum0 += ta;
            if (d1 + bias > 0.f) rowsum1 += ta;
            if (d2 + bias > 0.f) rowsum2 += ta;
            if (d3 + bias > 0.f) rowsum3 += ta;
        }
    }

    // ---- reduce across the 8 estimator-threads (consecutive lanes) ----
#pragma unroll
    for (int o = 1; o < 8; o <<= 1) {
        rowsum0 += __shfl_xor_sync(0xffffffffu, rowsum0, o);
        rowsum1 += __shfl_xor_sync(0xffffffffu, rowsum1, o);
        rowsum2 += __shfl_xor_sync(0xffffffffu, rowsum2, o);
        rowsum3 += __shfl_xor_sync(0xffffffffu, rowsum3, o);
    }

    if (et == 0) {
        int r = rowBase + rt * 4;
        float4 o;
        o.x = (rowsum0 > 0.f) ? 1.f : ((rowsum0 < 0.f) ? -1.f : 0.f);
        o.y = (rowsum1 > 0.f) ? 1.f : ((rowsum1 < 0.f) ? -1.f : 0.f);
        o.z = (rowsum2 > 0.f) ? 1.f : ((rowsum2 < 0.f) ? -1.f : 0.f);
        o.w = (rowsum3 > 0.f) ? 1.f : ((rowsum3 < 0.f) ? -1.f : 0.f);
        if (r + 3 < N) {
            *reinterpret_cast<float4*>(out + r) = o;
        } else {
            float ov[4] = {o.x, o.y, o.z, o.w};
            for (int i = 0; i < 4; i++)
                if (r + i < N) out[r + i] = ov[i];
        }
    }
}

// ============================================================
// Launch
// ============================================================
extern "C" void kernel_launch(void* const* d_in, const int* in_sizes, int n_in,
                              void* d_out, int out_size) {
    const float* x      = (const float*)d_in[0];
    const float* W      = (const float*)d_in[1];
    const float* b      = (const float*)d_in[2];
    const float* alphas = (const float*)d_in[3];
    float* out = (float*)d_out;

    int E = in_sizes[2];          // 256
    int N = out_size;             // 131072

    prep_kernel<<<1, 256>>>(alphas, b, E);
    packW_kernel<<<EMAX, 128>>>(W);
    int grid = (N + BR - 1) / BR;
    main_kernel<<<grid, 256>>>(x, out, N);
}

// round 4
// speedup vs baseline: 2.1730x; 2.1730x over previous
#include <cuda_runtime.h>
#include <cuda_fp16.h>
#include <cstdint>

// ================= problem constants =================
#define FDIM 512
#define EMAX 256

// scaling keeps lo-split parts in fp16 normal range; sign(logit) invariant
#define X_SCALE 256.0f
#define W_SCALE 4096.0f
#define B_SCALE (X_SCALE * W_SCALE)   // 2^20

// ================= device scratch ====================
__device__ int    g_nactive;
__device__ int    g_npass;
__device__ float  g_ta[EMAX];        // trunc(alpha), 0 in padding
__device__ float  g_bias[EMAX];      // bias * B_SCALE, 0 in padding
__device__ __half g_Wh[EMAX * FDIM]; // compacted W hi fp16 (scaled)
__device__ __half g_Wl[EMAX * FDIM]; // compacted W lo fp16 (scaled)

// ============================================================
// Prep kernel: compaction + W fp16 hi/lo packing (scaled).
// grid = EMAX blocks x 256 threads; every block redundantly computes the
// compaction (deterministic); block p packs compacted row p.
// ============================================================
__global__ __launch_bounds__(256) void pack_kernel(const float* __restrict__ W,
                                                   const float* __restrict__ bias,
                                                   const float* __restrict__ alphas,
                                                   int E) {
    __shared__ int   s_eidx[EMAX];
    __shared__ float s_ta[EMAX];
    __shared__ float s_b[EMAX];
    __shared__ int   wtot[8], woff[8];
    __shared__ int   s_nactive;

    int e = threadIdx.x;
    float ta = 0.f, bi = 0.f;
    int flag = 0;
    if (e < E) {
        ta = truncf(alphas[e]);
        bi = bias[e];
        flag = (ta != 0.f) ? 1 : 0;
    }
    unsigned mask = __ballot_sync(0xffffffffu, flag);
    int lane = e & 31, warp = e >> 5;
    int prefix = __popc(mask & ((1u << lane) - 1u));
    if (lane == 0) wtot[warp] = __popc(mask);
    s_eidx[e] = 0; s_ta[e] = 0.f; s_b[e] = 0.f;
    __syncthreads();
    if (e == 0) {
        int s = 0;
        for (int i = 0; i < 8; i++) { woff[i] = s; s += wtot[i]; }
        s_nactive = s;
    }
    __syncthreads();
    if (flag) {
        int pos = woff[warp] + prefix;
        s_eidx[pos] = e;
        s_ta[pos] = ta;
        s_b[pos] = bi * B_SCALE;
    }
    __syncthreads();

    int nactive = s_nactive;
    if (blockIdx.x == 0) {
        g_ta[e] = s_ta[e];
        g_bias[e] = s_b[e];
        if (e == 0) {
            g_nactive = nactive;
            int np = (nactive + 127) / 128;
            if (np < 1) np = 1;
            g_npass = np;
        }
    }

    // pack row p (256 threads x 2 floats = 512)
    int p = blockIdx.x;
    int t = threadIdx.x;
    if (p < nactive) {
        int src = s_eidx[p];
        float2 v = *reinterpret_cast<const float2*>(W + (size_t)src * FDIM + 2 * t);
        float s0 = v.x * W_SCALE;
        float s1 = v.y * W_SCALE;
        __half h0 = __float2half_rn(s0);
        __half h1 = __float2half_rn(s1);
        __half l0 = __float2half_rn(s0 - __half2float(h0));
        __half l1 = __float2half_rn(s1 - __half2float(h1));
        *reinterpret_cast<__half2*>(g_Wh + (size_t)p * FDIM + 2 * t) = __halves2half2(h0, h1);
        *reinterpret_cast<__half2*>(g_Wl + (size_t)p * FDIM + 2 * t) = __halves2half2(l0, l1);
    } else {
        __half2 z = __halves2half2(__ushort_as_half(0), __ushort_as_half(0));
        *reinterpret_cast<__half2*>(g_Wh + (size_t)p * FDIM + 2 * t) = z;
        *reinterpret_cast<__half2*>(g_Wl + (size_t)p * FDIM + 2 * t) = z;
    }
}

// ============================================================
// Main kernel: 128 rows/CTA x 128 est, K=512 in 8 chunks of 64,
// fp16 3-term split via mma.sync.m16n8k16 (HMMA), fp32 accum.
// 8 warps: warp = (mwarp 0..3) x (nwarp 0..1); warp tile m32 x n64.
// ============================================================
#define KC 64
#define NCHUNK (FDIM / KC)
#define STR 72                       // smem row stride in halves (bank-conflict-free)
#define TILE_H (128 * STR)           // halves per tile

__device__ __forceinline__ void mma16816(float* c, const uint32_t* a, const uint32_t* b) {
    asm volatile(
        "mma.sync.aligned.m16n8k16.row.col.f32.f16.f16.f32 "
        "{%0,%1,%2,%3}, {%4,%5,%6,%7}, {%8,%9}, {%0,%1,%2,%3};"
        : "+f"(c[0]), "+f"(c[1]), "+f"(c[2]), "+f"(c[3])
        : "r"(a[0]), "r"(a[1]), "r"(a[2]), "r"(a[3]), "r"(b[0]), "r"(b[1]));
}

__global__ __launch_bounds__(256, 1) void main_kernel(const float* __restrict__ x,
                                                      float* __restrict__ out,
                                                      int N) {
    extern __shared__ char smem_raw[];
    __half* xh = reinterpret_cast<__half*>(smem_raw);
    __half* xl = xh + TILE_H;
    __half* wh = xl + TILE_H;
    __half* wl = wh + TILE_H;
    float* votes = reinterpret_cast<float*>(wl + TILE_H);
    float* sbias = votes + 128;
    float* sta   = sbias + 128;

    const int tid = threadIdx.x;
    const int w = tid >> 5;
    const int lane = tid & 31;
    const int l4 = lane >> 2;      // 0..7
    const int lm = lane & 3;       // 0..3
    const int mwarp = w & 3;       // 0..3
    const int nwarp = w >> 2;      // 0..1
    const int mbase = mwarp * 32;
    const int nbase = nwarp * 64;
    const int rowBase = blockIdx.x * 128;

    if (tid < 128) votes[tid] = 0.f;

    const int npass = g_npass;

    for (int pass = 0; pass < npass; pass++) {
        // per-pass bias/alpha slices
        if (tid < 128) {
            int e = pass * 128 + tid;
            sbias[tid] = g_bias[e];
            sta[tid]   = g_ta[e];
        }

        float c[2][8][4];
#pragma unroll
        for (int mi = 0; mi < 2; mi++)
#pragma unroll
            for (int ni = 0; ni < 8; ni++)
#pragma unroll
                for (int j = 0; j < 4; j++) c[mi][ni][j] = 0.f;

        for (int kc = 0; kc < NCHUNK; kc++) {
            __syncthreads();   // protect smem tiles from previous iteration readers

            // ---- load + convert x chunk: 128 rows x 64 floats ----
            {
                int c4 = tid & 15;           // float4 col within chunk
                int rg = tid >> 4;           // 0..15
                const float* xb = x + (size_t)rowBase * FDIM + kc * KC + c4 * 4;
#pragma unroll
                for (int i = 0; i < 8; i++) {
                    int row = i * 16 + rg;
                    float4 v = make_float4(0.f, 0.f, 0.f, 0.f);
                    if (rowBase + row < N)
                        v = *reinterpret_cast<const float4*>(xb + (size_t)row * FDIM);
                    float s0 = v.x * X_SCALE, s1 = v.y * X_SCALE;
                    float s2 = v.z * X_SCALE, s3 = v.w * X_SCALE;
                    __half2 h01 = __floats2half2_rn(s0, s1);
                    __half2 h23 = __floats2half2_rn(s2, s3);
                    __half2 l01 = __floats2half2_rn(s0 - __low2float(h01), s1 - __high2float(h01));
                    __half2 l23 = __floats2half2_rn(s2 - __low2float(h23), s3 - __high2float(h23));
                    __half2* ph = reinterpret_cast<__half2*>(xh + row * STR + c4 * 4);
                    __half2* pl = reinterpret_cast<__half2*>(xl + row * STR + c4 * 4);
                    ph[0] = h01; ph[1] = h23;
                    pl[0] = l01; pl[1] = l23;
                }
            }
            // ---- load W chunk (fp16 prepacked): 2 tiles x 128 rows x 64 halves ----
            {
                // 2048 uint4 total / 256 threads = 8 each (4 wh + 4 wl)
                int u8 = tid & 7;            // 16B unit (8 per row)
                int rg = tid >> 3;           // 0..31
#pragma unroll
                for (int i = 0; i < 4; i++) {
                    int r = i * 32 + rg;
                    size_t goff = (size_t)(pass * 128 + r) * FDIM + kc * KC + u8 * 8;
                    uint4 vh = *reinterpret_cast<const uint4*>(g_Wh + goff);
                    uint4 vl = *reinterpret_cast<const uint4*>(g_Wl + goff);
                    *reinterpret_cast<uint4*>(wh + r * STR + u8 * 8) = vh;
                    *reinterpret_cast<uint4*>(wl + r * STR + u8 * 8) = vl;
                }
            }
            __syncthreads();

            // ---- 4 k16 steps ----
#pragma unroll
            for (int ks = 0; ks < 4; ks++) {
                const int k0 = ks * 16 + 2 * lm;   // half index
                uint32_t ah[2][4], al[2][4];
#pragma unroll
                for (int mi = 0; mi < 2; mi++) {
                    int r0 = mbase + mi * 16 + l4;
                    const __half* ph = xh + r0 * STR;
                    const __half* pl = xl + r0 * STR;
                    ah[mi][0] = *reinterpret_cast<const uint32_t*>(ph + k0);
                    ah[mi][1] = *reinterpret_cast<const uint32_t*>(ph + 8 * STR + k0);
                    ah[mi][2] = *reinterpret_cast<const uint32_t*>(ph + k0 + 8);
                    ah[mi][3] = *reinterpret_cast<const uint32_t*>(ph + 8 * STR + k0 + 8);
                    al[mi][0] = *reinterpret_cast<const uint32_t*>(pl + k0);
                    al[mi][1] = *reinterpret_cast<const uint32_t*>(pl + 8 * STR + k0);
                    al[mi][2] = *reinterpret_cast<const uint32_t*>(pl + k0 + 8);
                    al[mi][3] = *reinterpret_cast<const uint32_t*>(pl + 8 * STR + k0 + 8);
                }
                uint32_t bh[8][2], bl[8][2];
#pragma unroll
                for (int ni = 0; ni < 8; ni++) {
                    int col = nbase + ni * 8 + l4;
                    const __half* ph = wh + col * STR;
                    const __half* pl = wl + col * STR;
                    bh[ni][0] = *reinterpret_cast<const uint32_t*>(ph + k0);
                    bh[ni][1] = *reinterpret_cast<const uint32_t*>(ph + k0 + 8);
                    bl[ni][0] = *reinterpret_cast<const uint32_t*>(pl + k0);
                    bl[ni][1] = *reinterpret_cast<const uint32_t*>(pl + k0 + 8);
                }
#pragma unroll
                for (int mi = 0; mi < 2; mi++)
#pragma unroll
                    for (int ni = 0; ni < 8; ni++) {
                        mma16816(c[mi][ni], ah[mi], bh[ni]);
                        mma16816(c[mi][ni], ah[mi], bl[ni]);
                        mma16816(c[mi][ni], al[mi], bh[ni]);
                    }
            }
        }
        __syncthreads();   // sbias/sta visible; tiles done

        // ---- epilogue: threshold + weighted vote ----
        float acc[2][2] = {{0.f, 0.f}, {0.f, 0.f}};
#pragma unroll
        for (int mi = 0; mi < 2; mi++)
#pragma unroll
            for (int ni = 0; ni < 8; ni++) {
                int lc = nbase + ni * 8 + 2 * lm;
                float b0 = sbias[lc], b1 = sbias[lc + 1];
                float t0 = sta[lc],   t1 = sta[lc + 1];
                if (c[mi][ni][0] + b0 > 0.f) acc[mi][0] += t0;
                if (c[mi][ni][1] + b1 > 0.f) acc[mi][0] += t1;
                if (c[mi][ni][2] + b0 > 0.f) acc[mi][1] += t0;
                if (c[mi][ni][3] + b1 > 0.f) acc[mi][1] += t1;
            }
#pragma unroll
        for (int mi = 0; mi < 2; mi++) {
            atomicAdd(&votes[mbase + mi * 16 + l4], acc[mi][0]);
            atomicAdd(&votes[mbase + mi * 16 + l4 + 8], acc[mi][1]);
        }
        __syncthreads();
    }

    if (tid < 128) {
        int r = rowBase + tid;
        if (r < N) {
            float v = votes[tid];
            out[r] = (v > 0.f) ? 1.f : ((v < 0.f) ? -1.f : 0.f);
        }
    }
}

#define SMEM_BYTES (4 * TILE_H * 2 + (128 + 128 + 128) * 4 + 256)

// ============================================================
// Launch
// ============================================================
extern "C" void kernel_launch(void* const* d_in, const int* in_sizes, int n_in,
                              void* d_out, int out_size) {
    const float* x      = (const float*)d_in[0];
    const float* W      = (const float*)d_in[1];
    const float* b      = (const float*)d_in[2];
    const float* alphas = (const float*)d_in[3];
    float* out = (float*)d_out;

    int E = in_sizes[2];   // 256
    int N = out_size;      // 131072

    cudaFuncSetAttribute(main_kernel, cudaFuncAttributeMaxDynamicSharedMemorySize,
                         SMEM_BYTES);

    pack_kernel<<<EMAX, 256>>>(W, b, alphas, E);
    int grid = (N + 127) / 128;
    main_kernel<<<grid, 256, SMEM_BYTES>>>(x, out, N);
}